// round 5
// baseline (speedup 1.0000x reference)
#include <cuda_runtime.h>
#include <cuda_fp16.h>
#include <stdint.h>
#include <math.h>

#define N_TOK  32768
#define HID    1024
#define NEXP   64
#define H4     256
#define N_TOT  320

#define MT      128
#define KC      32
#define NCHUNK  (HID / KC)   // 32
#define THREADS 512

// smem: B 3 stages @ 40960 (hi 20480 + lo 20480), then A16 2 stages @ 16384 (hi 8192 + lo 8192)
#define B_STAGE   40960
#define A16_BASE  122880
#define A16_STAGE 16384
#define SMEM_TOTAL 155648

__device__ __align__(16) __half g_whi[N_TOT * HID];
__device__ __align__(16) __half g_wlo[N_TOT * HID];
__device__ float g_load[NEXP];
__device__ float g_ent;

__device__ __forceinline__ uint32_t smem_u32(const void* p) {
    uint32_t a;
    asm("{ .reg .u64 t; cvta.to.shared.u64 t, %1; cvt.u32.u64 %0, t; }" : "=r"(a) : "l"(p));
    return a;
}
__device__ __forceinline__ void cp16(uint32_t dst, const void* src) {
    asm volatile("cp.async.cg.shared.global [%0], [%1], 16;"
                 :: "r"(dst), "l"(__cvta_generic_to_global(src)));
}
__device__ __forceinline__ void ldsm4(uint32_t* r, uint32_t addr) {
    asm volatile("ldmatrix.sync.aligned.m8n8.x4.shared.b16 {%0,%1,%2,%3}, [%4];"
                 : "=r"(r[0]), "=r"(r[1]), "=r"(r[2]), "=r"(r[3]) : "r"(addr));
}
__device__ __forceinline__ void mma16816(float* c, const uint32_t* a, const uint32_t* b) {
    asm volatile(
        "mma.sync.aligned.m16n8k16.row.col.f32.f16.f16.f32 "
        "{%0,%1,%2,%3}, {%4,%5,%6,%7}, {%8,%9}, {%0,%1,%2,%3};"
        : "+f"(c[0]), "+f"(c[1]), "+f"(c[2]), "+f"(c[3])
        : "r"(a[0]), "r"(a[1]), "r"(a[2]), "r"(a[3]), "r"(b[0]), "r"(b[1]));
}
__device__ __forceinline__ uint32_t h2u(__half2 h) {
    uint32_t u; __builtin_memcpy(&u, &h, 4); return u;
}

// ---------------- prep: weights -> fp16 hi/lo, plus stat init ----------------
__global__ void prep_w_kernel(const float* __restrict__ RW, const float* __restrict__ W1) {
    int i = blockIdx.x * blockDim.x + threadIdx.x;
    if (blockIdx.x == 0) {
        if (threadIdx.x < NEXP) g_load[threadIdx.x] = 0.0f;
        if (threadIdx.x == 0)   g_ent = 0.0f;
    }
    if (i >= N_TOT * HID) return;
    int row = i >> 10;
    float v = (row < NEXP) ? RW[i] : W1[i - NEXP * HID];
    __half h = __float2half_rn(v);
    g_whi[i] = h;
    g_wlo[i] = __float2half_rn(v - __half2float(h));
}

// ---------------- fused GEMM + router epilogue ----------------
__global__ void __launch_bounds__(THREADS, 1)
gemm_kernel(const float* __restrict__ X,
            const float* __restrict__ B1, const float* __restrict__ W2,
            const float* __restrict__ B2,
            float* __restrict__ logits, float* __restrict__ sel, float* __restrict__ wts)
{
    extern __shared__ __align__(1024) char smem[];
    const uint32_t sbase = smem_u32(smem);
    const int tid = threadIdx.x;
    const int lane = tid & 31;
    const int wid = tid >> 5;
    const int wm = wid & 3;
    const int wn = wid >> 2;
    const int m0 = blockIdx.x * MT;

    float acc[2][10][4];
#pragma unroll
    for (int i = 0; i < 2; i++)
#pragma unroll
        for (int j = 0; j < 10; j++)
#pragma unroll
            for (int r = 0; r < 4; r++) acc[i][j][r] = 0.0f;

    // ldmatrix address precompute (64B rows)
    uint32_t aOff[2], aXor[2];
#pragma unroll
    for (int mt = 0; mt < 2; mt++) {
        int row = wm * 32 + mt * 16 + (lane & 15);
        aOff[mt] = (uint32_t)row * 64;
        aXor[mt] = ((uint32_t)row * 8) & 0x30;
    }
    const uint32_t aKB = ((lane >> 4) & 1) * 16;
    uint32_t bOff[5], bXor[5];
#pragma unroll
    for (int p = 0; p < 5; p++) {
        int n = wn * 80 + (p * 2 + ((lane >> 4) & 1)) * 8 + (lane & 7);
        bOff[p] = (uint32_t)n * 64;
        bXor[p] = ((uint32_t)n * 8) & 0x30;
    }
    const uint32_t bKB = ((lane >> 3) & 1) * 16;

    // B issue: 2560 16B-units per chunk, 5 per thread
    auto issueB = [&](int c) {
#pragma unroll
        for (int it = 0; it < 5; it++) {
            int j = tid + it * THREADS;
            int v = j >= 1280;
            int jj = v ? j - 1280 : j;
            int n = jj >> 2, g = jj & 3;
            const __half* src = (v ? g_wlo : g_whi) + (size_t)n * HID + c * KC + g * 8;
            uint32_t dst = sbase + (uint32_t)(c % 3) * B_STAGE + v * 20480 +
                           ((uint32_t)n * 64 + (((uint32_t)g * 16) ^ (((uint32_t)n * 8) & 0x30)));
            cp16(dst, src);
        }
        asm volatile("cp.async.commit_group;");
    };

    // A LDG: 2 float4 per thread per chunk (row = u>>3, granule g = u&7)
    const int ar0 = tid >> 3,        ag0 = tid & 7;
    const int ar1 = (tid + 512) >> 3, ag1 = (tid + 512) & 7;
    const float* aSrc0 = X + (size_t)(m0 + ar0) * HID + ag0 * 4;
    const float* aSrc1 = X + (size_t)(m0 + ar1) * HID + ag1 * 4;
    float4 fa0, fa1;
    auto ldgA = [&](int c) {
        fa0 = *reinterpret_cast<const float4*>(aSrc0 + c * KC);
        fa1 = *reinterpret_cast<const float4*>(aSrc1 + c * KC);
    };
    // cvt + STS one float4 (granule) into A16 stage
    auto stA = [&](uint32_t st, int row, int g, float4 f) {
        __half2 h0 = __floats2half2_rn(f.x, f.y);
        __half2 h1 = __floats2half2_rn(f.z, f.w);
        float2 g0 = __half22float2(h0), g1 = __half22float2(h1);
        __half2 l0 = __floats2half2_rn(f.x - g0.x, f.y - g0.y);
        __half2 l1 = __floats2half2_rn(f.z - g1.x, f.w - g1.y);
        uint32_t xr = ((uint32_t)row * 8) & 0x30;
        uint32_t off = (uint32_t)row * 64 + (((uint32_t)(g >> 1) * 16) ^ xr) + (g & 1) * 8;
        *reinterpret_cast<uint2*>(smem + (st - sbase) + off) = make_uint2(h2u(h0), h2u(h1));
        *reinterpret_cast<uint2*>(smem + (st - sbase) + 8192 + off) = make_uint2(h2u(l0), h2u(l1));
    };
    auto cvtA = [&](int c) {
        uint32_t st = sbase + A16_BASE + (uint32_t)(c & 1) * A16_STAGE;
        stA(st, ar0, ag0, fa0);
        stA(st, ar1, ag1, fa1);
    };

    // ---- prologue ----
    ldgA(0);
    issueB(0);
    issueB(1);
    cvtA(0);
    ldgA(1);
    asm volatile("cp.async.wait_group 1;");
    __syncthreads();

    // ---- mainloop: one barrier per chunk ----
    for (int c = 0; c < NCHUNK; c++) {
        if (c + 2 < NCHUNK) issueB(c + 2);
        else asm volatile("cp.async.commit_group;");

        const uint32_t aHi = sbase + A16_BASE + (uint32_t)(c & 1) * A16_STAGE;
        const uint32_t bHi = sbase + (uint32_t)(c % 3) * B_STAGE;
#pragma unroll
        for (int ks = 0; ks < 2; ks++) {
            const uint32_t kb = ks * 32;
            uint32_t ah[2][4], al[2][4], bb[5][4];
#pragma unroll
            for (int mt = 0; mt < 2; mt++)
                ldsm4(ah[mt], aHi + aOff[mt] + ((kb + aKB) ^ aXor[mt]));
#pragma unroll
            for (int p = 0; p < 5; p++)
                ldsm4(bb[p], bHi + bOff[p] + ((kb + bKB) ^ bXor[p]));
#pragma unroll
            for (int mt = 0; mt < 2; mt++)
#pragma unroll
                for (int p = 0; p < 5; p++) {
                    mma16816(acc[mt][p * 2 + 0], ah[mt], &bb[p][0]);
                    mma16816(acc[mt][p * 2 + 1], ah[mt], &bb[p][2]);
                }
#pragma unroll
            for (int mt = 0; mt < 2; mt++)
                ldsm4(al[mt], aHi + 8192 + aOff[mt] + ((kb + aKB) ^ aXor[mt]));
#pragma unroll
            for (int mt = 0; mt < 2; mt++)
#pragma unroll
                for (int p = 0; p < 5; p++) {
                    mma16816(acc[mt][p * 2 + 0], al[mt], &bb[p][0]);
                    mma16816(acc[mt][p * 2 + 1], al[mt], &bb[p][2]);
                }
#pragma unroll
            for (int p = 0; p < 5; p++)
                ldsm4(bb[p], bHi + 20480 + bOff[p] + ((kb + bKB) ^ bXor[p]));
#pragma unroll
            for (int mt = 0; mt < 2; mt++)
#pragma unroll
                for (int p = 0; p < 5; p++) {
                    mma16816(acc[mt][p * 2 + 0], ah[mt], &bb[p][0]);
                    mma16816(acc[mt][p * 2 + 1], ah[mt], &bb[p][2]);
                }
        }

        if (c + 1 < NCHUNK) cvtA(c + 1);
        if (c + 2 < NCHUNK) ldgA(c + 2);
        asm volatile("cp.async.wait_group 1;");
        __syncthreads();
    }

    // ---------------- fused epilogue ----------------
    float* s_log  = reinterpret_cast<float*>(smem);           // [128][68]
    float* s_u    = reinterpret_cast<float*>(smem + 34816);   // [128]
    float* s_load = s_u + 128;                                // [64]
    float* s_ent  = s_load + NEXP;

    if (tid < MT)   s_u[tid] = B2[0];
    if (tid < NEXP) s_load[tid] = 0.0f;
    if (tid == 0)   *s_ent = 0.0f;
    __syncthreads();

#pragma unroll
    for (int mt = 0; mt < 2; mt++) {
        float u0 = 0.0f, u1 = 0.0f;
        const int row0 = wm * 32 + mt * 16 + (lane >> 2);
#pragma unroll
        for (int nt = 0; nt < 10; nt++) {
            const int nb = wn * 80 + nt * 8 + (lane & 3) * 2;
            const bool is_logit = (wn == 0 && nt < 8);
#pragma unroll
            for (int r = 0; r < 4; r++) {
                const int n = nb + (r & 1);
                const float v = acc[mt][nt][r];
                if (is_logit) {
                    const int rl = row0 + ((r >= 2) ? 8 : 0);
                    s_log[rl * 68 + n] = v;
                } else {
                    const int h = n - 64;
                    const float hh = fmaxf(v + __ldg(B1 + h), 0.0f) * __ldg(W2 + h);
                    if (r < 2) u0 += hh; else u1 += hh;
                }
            }
        }
        u0 += __shfl_xor_sync(0xffffffffu, u0, 1);
        u0 += __shfl_xor_sync(0xffffffffu, u0, 2);
        u1 += __shfl_xor_sync(0xffffffffu, u1, 1);
        u1 += __shfl_xor_sync(0xffffffffu, u1, 2);
        if ((lane & 3) == 0) {
            atomicAdd(&s_u[row0], u0);
            atomicAdd(&s_u[row0 + 8], u1);
        }
    }
    __syncthreads();

    if (tid < MT) {
        const int m = m0 + tid;
        const float* row = s_log + tid * 68;

        float v0 = -INFINITY, v1 = -INFINITY, v2 = -INFINITY, v3 = -INFINITY;
        int i0 = 0, i1 = 0, i2 = 0, i3 = 0;
#pragma unroll
        for (int j = 0; j < NEXP; j++) {
            float x = row[j];
            if (x > v3) {
                if (x > v0)      { v3=v2;i3=i2; v2=v1;i2=i1; v1=v0;i1=i0; v0=x;i0=j; }
                else if (x > v1) { v3=v2;i3=i2; v2=v1;i2=i1; v1=x;i1=j; }
                else if (x > v2) { v3=v2;i3=i2; v2=x;i2=j; }
                else             { v3=x;i3=j; }
            }
        }
        float ex[NEXP];
        float se = 0.0f;
#pragma unroll
        for (int j = 0; j < NEXP; j++) { ex[j] = __expf(row[j] - v0); se += ex[j]; }
        float inv = 1.0f / se;
        float ent = 0.0f;
#pragma unroll
        for (int jj = 0; jj < NEXP; jj++) {
            int e = (jj + tid) & 63;
            float p = ex[e] * inv;
            ent -= p * __logf(p + 1e-8f);
            atomicAdd(&s_load[e], p);
        }
        atomicAdd(s_ent, ent);

        float u = s_u[tid];
        float cplx = 1.0f / (1.0f + expf(-u));
        int kk = (cplx > 0.5f) ? 4 : 1;
        float e0 = 1.0f;
        float e1 = (kk > 1) ? expf(v1 - v0) : 0.0f;
        float e2 = (kk > 2) ? expf(v2 - v0) : 0.0f;
        float e3 = (kk > 3) ? expf(v3 - v0) : 0.0f;
        float wi = 1.0f / (e0 + e1 + e2 + e3);

        *reinterpret_cast<float4*>(sel + (size_t)m * 4) =
            make_float4((float)i0, (float)((kk > 1) ? i1 : 0),
                        (float)((kk > 2) ? i2 : 0), (float)((kk > 3) ? i3 : 0));
        *reinterpret_cast<float4*>(wts + (size_t)m * 4) =
            make_float4(e0 * wi, e1 * wi, e2 * wi, e3 * wi);
    } else {
        for (int t = tid - MT; t < MT * 16; t += (THREADS - MT)) {
            int r = t >> 4, c4 = t & 15;
            float4 v = *reinterpret_cast<const float4*>(s_log + r * 68 + c4 * 4);
            *reinterpret_cast<float4*>(logits + (size_t)(m0 + r) * NEXP + c4 * 4) = v;
        }
    }
    __syncthreads();

    if (tid < NEXP) atomicAdd(&g_load[tid], s_load[tid]);
    if (tid == 0)   atomicAdd(&g_ent, *s_ent);
}

// ---------------- finalize ----------------
__global__ void finalize_kernel(float* __restrict__ out_var, float* __restrict__ out_ent) {
    if (threadIdx.x == 0) {
        float xs[NEXP];
        float mean = 0.0f;
        for (int e = 0; e < NEXP; e++) { xs[e] = g_load[e] * (1.0f / N_TOK); mean += xs[e]; }
        mean *= (1.0f / NEXP);
        float var = 0.0f;
        for (int e = 0; e < NEXP; e++) { float d = xs[e] - mean; var += d * d; }
        out_var[0] = var * (1.0f / (NEXP - 1));
        out_ent[0] = g_ent * (1.0f / N_TOK);
    }
}

// ---------------- launch ----------------
extern "C" void kernel_launch(void* const* d_in, const int* in_sizes, int n_in,
                              void* d_out, int out_size) {
    const float* X  = (const float*)d_in[0];
    const float* RW = (const float*)d_in[1];
    const float* W1 = (const float*)d_in[2];
    const float* B1 = (const float*)d_in[3];
    const float* W2 = (const float*)d_in[4];
    const float* B2 = (const float*)d_in[5];

    float* out    = (float*)d_out;
    float* logits = out;
    float* sel    = logits + (size_t)N_TOK * NEXP;
    float* wts    = sel + (size_t)N_TOK * 4;
    float* ovar   = wts + (size_t)N_TOK * 4;
    float* oent   = ovar + 1;

    cudaFuncSetAttribute(gemm_kernel, cudaFuncAttributeMaxDynamicSharedMemorySize, SMEM_TOTAL);

    prep_w_kernel<<<(N_TOT * HID + 255) / 256, 256>>>(RW, W1);
    gemm_kernel<<<N_TOK / MT, THREADS, SMEM_TOTAL>>>(X, B1, W2, B2, logits, sel, wts);
    finalize_kernel<<<1, 32>>>(ovar, oent);
}

// round 6
// speedup vs baseline: 1.7300x; 1.7300x over previous
#include <cuda_runtime.h>
#include <cuda_fp16.h>
#include <stdint.h>
#include <math.h>

#define N_TOK  32768
#define HID    1024
#define NEXP   64
#define H4     256
#define N_TOT  320          // 64 router + 256 hidden

#define MT      128         // M rows per CTA
#define KC      64          // K per chunk
#define NCHUNK  (HID / KC)  // 16
#define THREADS 512

// smem stage layout (bytes) — identical to round 3
#define A_HI   0
#define A_LO   16384
#define B_HI   32768
#define B_LO   73728
#define ST_BYTES 114688
#define SMEM_TOTAL (2 * ST_BYTES)   // 229376

// ---------------- device scratch ----------------
__device__ __align__(16) __half g_xhi[(size_t)N_TOK * HID];
__device__ __align__(16) __half g_xlo[(size_t)N_TOK * HID];
__device__ __align__(16) __half g_whi[N_TOT * HID];
__device__ __align__(16) __half g_wlo[N_TOT * HID];
__device__ float g_load[NEXP];
__device__ float g_ent;

__device__ __forceinline__ uint32_t swz(uint32_t o) { return o ^ ((o >> 3) & 0x70); }
__device__ __forceinline__ uint32_t smem_u32(const void* p) {
    uint32_t a;
    asm("{ .reg .u64 t; cvta.to.shared.u64 t, %1; cvt.u32.u64 %0, t; }" : "=r"(a) : "l"(p));
    return a;
}
__device__ __forceinline__ void cp16(uint32_t dst, const void* src) {
    asm volatile("cp.async.cg.shared.global [%0], [%1], 16;"
                 :: "r"(dst), "l"(__cvta_generic_to_global(src)));
}
__device__ __forceinline__ void ldsm4(uint32_t* r, uint32_t addr) {
    asm volatile("ldmatrix.sync.aligned.m8n8.x4.shared.b16 {%0,%1,%2,%3}, [%4];"
                 : "=r"(r[0]), "=r"(r[1]), "=r"(r[2]), "=r"(r[3]) : "r"(addr));
}
__device__ __forceinline__ void mma16816(float* c, const uint32_t* a, const uint32_t* b) {
    asm volatile(
        "mma.sync.aligned.m16n8k16.row.col.f32.f16.f16.f32 "
        "{%0,%1,%2,%3}, {%4,%5,%6,%7}, {%8,%9}, {%0,%1,%2,%3};"
        : "+f"(c[0]), "+f"(c[1]), "+f"(c[2]), "+f"(c[3])
        : "r"(a[0]), "r"(a[1]), "r"(a[2]), "r"(a[3]), "r"(b[0]), "r"(b[1]));
}
__device__ __forceinline__ uint32_t h2u(__half2 h) {
    uint32_t u; __builtin_memcpy(&u, &h, 4); return u;
}

// ---------------- prep: W + X -> fp16 hi/lo (uint4 stores) + stat init ----------------
#define W_UNITS (N_TOT * HID / 8)       // 40960
#define W_BLOCKS (W_UNITS / 256)        // 160
#define X_BLOCKS (N_TOK * HID / 8 / 256)  // 16384

__global__ void prep_kernel(const float* __restrict__ X,
                            const float* __restrict__ RW, const float* __restrict__ W1) {
    if (blockIdx.x == 0 && threadIdx.x < NEXP) {
        g_load[threadIdx.x] = 0.0f;
        if (threadIdx.x == 0) g_ent = 0.0f;
    }
    const bool isW = blockIdx.x < W_BLOCKS;
    size_t u = isW ? ((size_t)blockIdx.x * 256 + threadIdx.x)
                   : ((size_t)(blockIdx.x - W_BLOCKS) * 256 + threadIdx.x);
    const float* src;
    __half *dhi, *dlo;
    if (isW) {
        size_t e = u * 8;
        int row = (int)(e >> 10);
        src = (row < NEXP) ? (RW + e) : (W1 + e - (size_t)NEXP * HID);
        dhi = g_whi + e; dlo = g_wlo + e;
    } else {
        src = X + u * 8;
        dhi = g_xhi + u * 8; dlo = g_xlo + u * 8;
    }
    float4 f0 = reinterpret_cast<const float4*>(src)[0];
    float4 f1 = reinterpret_cast<const float4*>(src)[1];
    __half2 h0 = __floats2half2_rn(f0.x, f0.y);
    __half2 h1 = __floats2half2_rn(f0.z, f0.w);
    __half2 h2 = __floats2half2_rn(f1.x, f1.y);
    __half2 h3 = __floats2half2_rn(f1.z, f1.w);
    float2 g0 = __half22float2(h0), g1 = __half22float2(h1);
    float2 g2 = __half22float2(h2), g3 = __half22float2(h3);
    __half2 l0 = __floats2half2_rn(f0.x - g0.x, f0.y - g0.y);
    __half2 l1 = __floats2half2_rn(f0.z - g1.x, f0.w - g1.y);
    __half2 l2 = __floats2half2_rn(f1.x - g2.x, f1.y - g2.y);
    __half2 l3 = __floats2half2_rn(f1.z - g3.x, f1.w - g3.y);
    *reinterpret_cast<uint4*>(dhi) = make_uint4(h2u(h0), h2u(h1), h2u(h2), h2u(h3));
    *reinterpret_cast<uint4*>(dlo) = make_uint4(h2u(l0), h2u(l1), h2u(l2), h2u(l3));
}

// ---------------- GEMM (round-3 mainloop) + fused router epilogue ----------------
__global__ void __launch_bounds__(THREADS, 1)
gemm_kernel(const float* __restrict__ B1, const float* __restrict__ W2,
            const float* __restrict__ B2,
            float* __restrict__ logits, float* __restrict__ sel, float* __restrict__ wts)
{
    extern __shared__ __align__(1024) char smem[];
    const uint32_t sbase = smem_u32(smem);
    const int tid = threadIdx.x;
    const int lane = tid & 31;
    const int wid = tid >> 5;
    const int wm = wid & 3;
    const int wn = wid >> 2;
    const int m0 = blockIdx.x * MT;

    float acc[2][10][4];
#pragma unroll
    for (int i = 0; i < 2; i++)
#pragma unroll
        for (int j = 0; j < 10; j++)
#pragma unroll
            for (int r = 0; r < 4; r++) acc[i][j][r] = 0.0f;

    uint32_t aBase[2], aXor[2];
#pragma unroll
    for (int mt = 0; mt < 2; mt++) {
        int row = wm * 32 + mt * 16 + (lane & 15);
        aBase[mt] = (uint32_t)row * 128;
        aXor[mt] = ((uint32_t)row * 16) & 0x70;
    }
    const uint32_t aKB = ((lane >> 4) & 1) * 16;

    uint32_t bBase[5], bXor[5];
#pragma unroll
    for (int p = 0; p < 5; p++) {
        int row = wn * 80 + (p * 2 + ((lane >> 4) & 1)) * 8 + (lane & 7);
        bBase[p] = (uint32_t)row * 128;
        bXor[p] = ((uint32_t)row * 16) & 0x70;
    }
    const uint32_t bKB = ((lane >> 3) & 1) * 16;

    auto issue = [&](int c) {
        const uint32_t sb = sbase + (c & 1) * ST_BYTES;
        const size_t k0 = (size_t)c * KC;
#pragma unroll
        for (int it = 0; it < 14; it++) {
            int u = tid + it * THREADS;
            const __half* src;
            uint32_t dst;
            if (u < 2048) {
                int v = u >> 10, j = u & 1023;
                int row = j >> 3, cq = j & 7;
                src = (v ? g_xlo : g_xhi) + (size_t)(m0 + row) * HID + k0 + cq * 8;
                dst = sb + (v ? A_LO : A_HI) + swz(row * 128 + cq * 16);
            } else {
                int t = u - 2048;
                int v = t >= 2560;
                int j = v ? t - 2560 : t;
                int row = j >> 3, cq = j & 7;
                src = (v ? g_wlo : g_whi) + (size_t)row * HID + k0 + cq * 8;
                dst = sb + (v ? B_LO : B_HI) + swz(row * 128 + cq * 16);
            }
            cp16(dst, src);
        }
        asm volatile("cp.async.commit_group;");
    };

    issue(0);

    for (int c = 0; c < NCHUNK; c++) {
        if (c + 1 < NCHUNK) {
            issue(c + 1);
            asm volatile("cp.async.wait_group 1;");
        } else {
            asm volatile("cp.async.wait_group 0;");
        }
        __syncthreads();

        const uint32_t sb = sbase + (c & 1) * ST_BYTES;
#pragma unroll
        for (int ks = 0; ks < 4; ks++) {
            const uint32_t kb = ks * 32;
            uint32_t ah[2][4], al[2][4], bb[5][4];
#pragma unroll
            for (int mt = 0; mt < 2; mt++)
                ldsm4(ah[mt], sb + A_HI + aBase[mt] + ((kb + aKB) ^ aXor[mt]));
#pragma unroll
            for (int p = 0; p < 5; p++)
                ldsm4(bb[p], sb + B_HI + bBase[p] + ((kb + bKB) ^ bXor[p]));
#pragma unroll
            for (int mt = 0; mt < 2; mt++)
#pragma unroll
                for (int p = 0; p < 5; p++) {
                    mma16816(acc[mt][p * 2 + 0], ah[mt], &bb[p][0]);
                    mma16816(acc[mt][p * 2 + 1], ah[mt], &bb[p][2]);
                }
#pragma unroll
            for (int mt = 0; mt < 2; mt++)
                ldsm4(al[mt], sb + A_LO + aBase[mt] + ((kb + aKB) ^ aXor[mt]));
#pragma unroll
            for (int mt = 0; mt < 2; mt++)
#pragma unroll
                for (int p = 0; p < 5; p++) {
                    mma16816(acc[mt][p * 2 + 0], al[mt], &bb[p][0]);
                    mma16816(acc[mt][p * 2 + 1], al[mt], &bb[p][2]);
                }
#pragma unroll
            for (int p = 0; p < 5; p++)
                ldsm4(bb[p], sb + B_LO + bBase[p] + ((kb + bKB) ^ bXor[p]));
#pragma unroll
            for (int mt = 0; mt < 2; mt++)
#pragma unroll
                for (int p = 0; p < 5; p++) {
                    mma16816(acc[mt][p * 2 + 0], ah[mt], &bb[p][0]);
                    mma16816(acc[mt][p * 2 + 1], ah[mt], &bb[p][2]);
                }
        }
        __syncthreads();
    }

    // ---------------- fused epilogue ----------------
    float* s_log  = reinterpret_cast<float*>(smem);           // [128][68]
    float* s_u    = reinterpret_cast<float*>(smem + 34816);   // [128]
    float* s_load = s_u + 128;                                // [64]
    float* s_ent  = s_load + NEXP;

    if (tid < MT)   s_u[tid] = B2[0];
    if (tid < NEXP) s_load[tid] = 0.0f;
    if (tid == 0)   *s_ent = 0.0f;
    __syncthreads();

    // phase A: logits -> smem, hidden -> u partials
#pragma unroll
    for (int mt = 0; mt < 2; mt++) {
        float u0 = 0.0f, u1 = 0.0f;
        const int row0 = wm * 32 + mt * 16 + (lane >> 2);
#pragma unroll
        for (int nt = 0; nt < 10; nt++) {
            const int nb = wn * 80 + nt * 8 + (lane & 3) * 2;
            const bool is_logit = (wn == 0 && nt < 8);
#pragma unroll
            for (int r = 0; r < 4; r++) {
                const int n = nb + (r & 1);
                const float v = acc[mt][nt][r];
                if (is_logit) {
                    const int rl = row0 + ((r >= 2) ? 8 : 0);
                    s_log[rl * 68 + n] = v;
                } else {
                    const int h = n - 64;
                    const float hh = fmaxf(v + __ldg(B1 + h), 0.0f) * __ldg(W2 + h);
                    if (r < 2) u0 += hh; else u1 += hh;
                }
            }
        }
        u0 += __shfl_xor_sync(0xffffffffu, u0, 1);
        u0 += __shfl_xor_sync(0xffffffffu, u0, 2);
        u1 += __shfl_xor_sync(0xffffffffu, u1, 1);
        u1 += __shfl_xor_sync(0xffffffffu, u1, 2);
        if ((lane & 3) == 0) {
            atomicAdd(&s_u[row0], u0);
            atomicAdd(&s_u[row0 + 8], u1);
        }
    }
    __syncthreads();

    // phase B: all threads store logits to global (2048 float4)
#pragma unroll
    for (int it = 0; it < 4; it++) {
        int t = tid + it * THREADS;
        int r = t >> 4, c4 = t & 15;
        float4 v = *reinterpret_cast<const float4*>(s_log + r * 68 + c4 * 4);
        *reinterpret_cast<float4*>(logits + (size_t)(m0 + r) * NEXP + c4 * 4) = v;
    }
    __syncthreads();

    // phase C: per-token top-k / softmax / stats (token = tid), smem in place
    if (tid < MT) {
        const int m = m0 + tid;
        float* row = s_log + tid * 68;

        float v0 = -INFINITY, v1 = -INFINITY, v2 = -INFINITY, v3 = -INFINITY;
        int i0 = 0, i1 = 0, i2 = 0, i3 = 0;
#pragma unroll
        for (int j = 0; j < NEXP; j++) {
            float x = row[j];
            if (x > v3) {
                if (x > v0)      { v3=v2;i3=i2; v2=v1;i2=i1; v1=v0;i1=i0; v0=x;i0=j; }
                else if (x > v1) { v3=v2;i3=i2; v2=v1;i2=i1; v1=x;i1=j; }
                else if (x > v2) { v3=v2;i3=i2; v2=x;i2=j; }
                else             { v3=x;i3=j; }
            }
        }
        float se = 0.0f;
#pragma unroll
        for (int j = 0; j < NEXP; j++) {
            float e = __expf(row[j] - v0);
            se += e;
            row[j] = e;            // overwrite in place (logits already in global)
        }
        float inv = 1.0f / se;
        float ent = 0.0f;
#pragma unroll
        for (int jj = 0; jj < NEXP; jj++) {
            int e = (jj + tid) & 63;
            float p = row[e] * inv;
            ent -= p * __logf(p + 1e-8f);
            atomicAdd(&s_load[e], p);
        }
        atomicAdd(s_ent, ent);

        float u = s_u[tid];
        float cplx = 1.0f / (1.0f + expf(-u));
        int kk = (cplx > 0.5f) ? 4 : 1;
        float e0 = 1.0f;
        float e1 = (kk > 1) ? expf(v1 - v0) : 0.0f;
        float e2 = (kk > 2) ? expf(v2 - v0) : 0.0f;
        float e3 = (kk > 3) ? expf(v3 - v0) : 0.0f;
        float wi = 1.0f / (e0 + e1 + e2 + e3);

        *reinterpret_cast<float4*>(sel + (size_t)m * 4) =
            make_float4((float)i0, (float)((kk > 1) ? i1 : 0),
                        (float)((kk > 2) ? i2 : 0), (float)((kk > 3) ? i3 : 0));
        *reinterpret_cast<float4*>(wts + (size_t)m * 4) =
            make_float4(e0 * wi, e1 * wi, e2 * wi, e3 * wi);
    }
    __syncthreads();

    if (tid < NEXP) atomicAdd(&g_load[tid], s_load[tid]);
    if (tid == 0)   atomicAdd(&g_ent, *s_ent);
}

// ---------------- finalize ----------------
__global__ void finalize_kernel(float* __restrict__ out_var, float* __restrict__ out_ent) {
    if (threadIdx.x == 0) {
        float xs[NEXP];
        float mean = 0.0f;
        for (int e = 0; e < NEXP; e++) { xs[e] = g_load[e] * (1.0f / N_TOK); mean += xs[e]; }
        mean *= (1.0f / NEXP);
        float var = 0.0f;
        for (int e = 0; e < NEXP; e++) { float d = xs[e] - mean; var += d * d; }
        out_var[0] = var * (1.0f / (NEXP - 1));
        out_ent[0] = g_ent * (1.0f / N_TOK);
    }
}

// ---------------- launch ----------------
extern "C" void kernel_launch(void* const* d_in, const int* in_sizes, int n_in,
                              void* d_out, int out_size) {
    const float* X  = (const float*)d_in[0];
    const float* RW = (const float*)d_in[1];
    const float* W1 = (const float*)d_in[2];
    const float* B1 = (const float*)d_in[3];
    const float* W2 = (const float*)d_in[4];
    const float* B2 = (const float*)d_in[5];

    float* out    = (float*)d_out;
    float* logits = out;
    float* sel    = logits + (size_t)N_TOK * NEXP;
    float* wts    = sel + (size_t)N_TOK * 4;
    float* ovar   = wts + (size_t)N_TOK * 4;
    float* oent   = ovar + 1;

    cudaFuncSetAttribute(gemm_kernel, cudaFuncAttributeMaxDynamicSharedMemorySize, SMEM_TOTAL);

    prep_kernel<<<W_BLOCKS + X_BLOCKS, 256>>>(X, RW, W1);
    gemm_kernel<<<N_TOK / MT, THREADS, SMEM_TOTAL>>>(B1, W2, B2, logits, sel, wts);
    finalize_kernel<<<1, 32>>>(ovar, oent);
}

// round 7
// speedup vs baseline: 1.7937x; 1.0369x over previous
#include <cuda_runtime.h>
#include <cuda_fp16.h>
#include <stdint.h>
#include <math.h>

#define N_TOK  32768
#define HID    1024
#define NEXP   64
#define H4     256
#define N_TOT  320          // 64 router + 256 hidden

#define MT      128         // M rows per CTA
#define KC      32          // K per chunk
#define NCHUNK  (HID / KC)  // 32
#define THREADS 512

// smem stage layout (bytes): A_HI 8K | A_LO 8K | B_HI 20K | B_LO 20K = 57344
#define A_LO_OFF 8192
#define B_HI_OFF 16384
#define B_LO_OFF 36864
#define ST_BYTES 57344
#define NSTAGE   4
#define SMEM_TOTAL (NSTAGE * ST_BYTES)   // 229376

// ---------------- device scratch ----------------
__device__ __align__(16) __half g_xhi[(size_t)N_TOK * HID];
__device__ __align__(16) __half g_xlo[(size_t)N_TOK * HID];
__device__ __align__(16) __half g_whi[N_TOT * HID];
__device__ __align__(16) __half g_wlo[N_TOT * HID];
__device__ float g_load[NEXP];
__device__ float g_ent;

__device__ __forceinline__ uint32_t smem_u32(const void* p) {
    uint32_t a;
    asm("{ .reg .u64 t; cvta.to.shared.u64 t, %1; cvt.u32.u64 %0, t; }" : "=r"(a) : "l"(p));
    return a;
}
__device__ __forceinline__ void cp16(uint32_t dst, const void* src) {
    asm volatile("cp.async.cg.shared.global [%0], [%1], 16;"
                 :: "r"(dst), "l"(__cvta_generic_to_global(src)));
}
__device__ __forceinline__ void ldsm4(uint32_t* r, uint32_t addr) {
    asm volatile("ldmatrix.sync.aligned.m8n8.x4.shared.b16 {%0,%1,%2,%3}, [%4];"
                 : "=r"(r[0]), "=r"(r[1]), "=r"(r[2]), "=r"(r[3]) : "r"(addr));
}
__device__ __forceinline__ void mma16816(float* c, const uint32_t* a, const uint32_t* b) {
    asm volatile(
        "mma.sync.aligned.m16n8k16.row.col.f32.f16.f16.f32 "
        "{%0,%1,%2,%3}, {%4,%5,%6,%7}, {%8,%9}, {%0,%1,%2,%3};"
        : "+f"(c[0]), "+f"(c[1]), "+f"(c[2]), "+f"(c[3])
        : "r"(a[0]), "r"(a[1]), "r"(a[2]), "r"(a[3]), "r"(b[0]), "r"(b[1]));
}
__device__ __forceinline__ uint32_t h2u(__half2 h) {
    uint32_t u; __builtin_memcpy(&u, &h, 4); return u;
}

// ---------------- prep: W + X -> fp16 hi/lo + stat init ----------------
#define W_UNITS (N_TOT * HID / 8)          // 40960
#define W_BLOCKS (W_UNITS / 256)           // 160
#define X_BLOCKS (N_TOK * HID / 8 / 256)   // 16384

__global__ void prep_kernel(const float* __restrict__ X,
                            const float* __restrict__ RW, const float* __restrict__ W1) {
    if (blockIdx.x == 0 && threadIdx.x < NEXP) {
        g_load[threadIdx.x] = 0.0f;
        if (threadIdx.x == 0) g_ent = 0.0f;
    }
    const bool isW = blockIdx.x < W_BLOCKS;
    size_t u = isW ? ((size_t)blockIdx.x * 256 + threadIdx.x)
                   : ((size_t)(blockIdx.x - W_BLOCKS) * 256 + threadIdx.x);
    const float* src;
    __half *dhi, *dlo;
    if (isW) {
        size_t e = u * 8;
        int row = (int)(e >> 10);
        src = (row < NEXP) ? (RW + e) : (W1 + e - (size_t)NEXP * HID);
        dhi = g_whi + e; dlo = g_wlo + e;
    } else {
        src = X + u * 8;
        dhi = g_xhi + u * 8; dlo = g_xlo + u * 8;
    }
    float4 f0 = reinterpret_cast<const float4*>(src)[0];
    float4 f1 = reinterpret_cast<const float4*>(src)[1];
    __half2 h0 = __floats2half2_rn(f0.x, f0.y);
    __half2 h1 = __floats2half2_rn(f0.z, f0.w);
    __half2 h2 = __floats2half2_rn(f1.x, f1.y);
    __half2 h3 = __floats2half2_rn(f1.z, f1.w);
    float2 g0 = __half22float2(h0), g1 = __half22float2(h1);
    float2 g2 = __half22float2(h2), g3 = __half22float2(h3);
    __half2 l0 = __floats2half2_rn(f0.x - g0.x, f0.y - g0.y);
    __half2 l1 = __floats2half2_rn(f0.z - g1.x, f0.w - g1.y);
    __half2 l2 = __floats2half2_rn(f1.x - g2.x, f1.y - g2.y);
    __half2 l3 = __floats2half2_rn(f1.z - g3.x, f1.w - g3.y);
    *reinterpret_cast<uint4*>(dhi) = make_uint4(h2u(h0), h2u(h1), h2u(h2), h2u(h3));
    *reinterpret_cast<uint4*>(dlo) = make_uint4(h2u(l0), h2u(l1), h2u(l2), h2u(l3));
}

// ---------------- GEMM (4-stage pipeline) + fused router epilogue ----------------
__global__ void __launch_bounds__(THREADS, 1)
gemm_kernel(const float* __restrict__ B1, const float* __restrict__ W2,
            const float* __restrict__ B2,
            float* __restrict__ logits, float* __restrict__ sel, float* __restrict__ wts)
{
    extern __shared__ __align__(1024) char smem[];
    const uint32_t sbase = smem_u32(smem);
    const int tid = threadIdx.x;
    const int lane = tid & 31;
    const int wid = tid >> 5;
    const int wm = wid & 3;
    const int wn = wid >> 2;
    const int m0 = blockIdx.x * MT;

    float acc[2][10][4];
#pragma unroll
    for (int i = 0; i < 2; i++)
#pragma unroll
        for (int j = 0; j < 10; j++)
#pragma unroll
            for (int r = 0; r < 4; r++) acc[i][j][r] = 0.0f;

    // ldmatrix address precompute (64B rows)
    uint32_t aOff[2], aXor[2];
#pragma unroll
    for (int mt = 0; mt < 2; mt++) {
        int row = wm * 32 + mt * 16 + (lane & 15);
        aOff[mt] = (uint32_t)row * 64;
        aXor[mt] = ((uint32_t)row * 8) & 0x30;
    }
    const uint32_t aKB = ((lane >> 4) & 1) * 16;
    uint32_t bOff[5], bXor[5];
#pragma unroll
    for (int p = 0; p < 5; p++) {
        int n = wn * 80 + (p * 2 + ((lane >> 4) & 1)) * 8 + (lane & 7);
        bOff[p] = (uint32_t)n * 64;
        bXor[p] = ((uint32_t)n * 8) & 0x30;
    }
    const uint32_t bKB = ((lane >> 3) & 1) * 16;

    // chunk issue: 3584 16B-units, 7 per thread; always commits a group
    auto issue = [&](int c) {
        if (c < NCHUNK) {
            const uint32_t sb = sbase + (uint32_t)(c & 3) * ST_BYTES;
            const size_t k0 = (size_t)c * KC;
#pragma unroll
            for (int it = 0; it < 7; it++) {
                int u = tid + it * THREADS;
                const __half* src;
                uint32_t dst;
                if (u < 1024) {
                    int v = u >= 512;
                    int j = v ? u - 512 : u;
                    int row = j >> 2, g = j & 3;
                    src = (v ? g_xlo : g_xhi) + (size_t)(m0 + row) * HID + k0 + g * 8;
                    dst = sb + v * A_LO_OFF +
                          ((uint32_t)row * 64 + (((uint32_t)g * 16) ^ (((uint32_t)row * 8) & 0x30)));
                } else {
                    int t = u - 1024;
                    int v = t >= 1280;
                    int j = v ? t - 1280 : t;
                    int n = j >> 2, g = j & 3;
                    src = (v ? g_wlo : g_whi) + (size_t)n * HID + k0 + g * 8;
                    dst = sb + (v ? B_LO_OFF : B_HI_OFF) +
                          ((uint32_t)n * 64 + (((uint32_t)g * 16) ^ (((uint32_t)n * 8) & 0x30)));
                }
                cp16(dst, src);
            }
        }
        asm volatile("cp.async.commit_group;");
    };

    // prologue: 3 chunks in flight
    issue(0); issue(1); issue(2);

    for (int c = 0; c < NCHUNK; c++) {
        asm volatile("cp.async.wait_group 2;");   // group c complete
        __syncthreads();                          // everyone done reading stage (c-1)&3
        issue(c + 3);                             // overwrites stage (c-1)&3 — safe now

        const uint32_t sb = sbase + (uint32_t)(c & 3) * ST_BYTES;
#pragma unroll
        for (int ks = 0; ks < 2; ks++) {
            const uint32_t kb = ks * 32;
            uint32_t ah[2][4], al[2][4], bb[5][4];
#pragma unroll
            for (int mt = 0; mt < 2; mt++)
                ldsm4(ah[mt], sb + aOff[mt] + ((kb + aKB) ^ aXor[mt]));
#pragma unroll
            for (int p = 0; p < 5; p++)
                ldsm4(bb[p], sb + B_HI_OFF + bOff[p] + ((kb + bKB) ^ bXor[p]));
#pragma unroll
            for (int mt = 0; mt < 2; mt++)
#pragma unroll
                for (int p = 0; p < 5; p++) {
                    mma16816(acc[mt][p * 2 + 0], ah[mt], &bb[p][0]);
                    mma16816(acc[mt][p * 2 + 1], ah[mt], &bb[p][2]);
                }
#pragma unroll
            for (int mt = 0; mt < 2; mt++)
                ldsm4(al[mt], sb + A_LO_OFF + aOff[mt] + ((kb + aKB) ^ aXor[mt]));
#pragma unroll
            for (int mt = 0; mt < 2; mt++)
#pragma unroll
                for (int p = 0; p < 5; p++) {
                    mma16816(acc[mt][p * 2 + 0], al[mt], &bb[p][0]);
                    mma16816(acc[mt][p * 2 + 1], al[mt], &bb[p][2]);
                }
#pragma unroll
            for (int p = 0; p < 5; p++)
                ldsm4(bb[p], sb + B_LO_OFF + bOff[p] + ((kb + bKB) ^ bXor[p]));
#pragma unroll
            for (int mt = 0; mt < 2; mt++)
#pragma unroll
                for (int p = 0; p < 5; p++) {
                    mma16816(acc[mt][p * 2 + 0], ah[mt], &bb[p][0]);
                    mma16816(acc[mt][p * 2 + 1], ah[mt], &bb[p][2]);
                }
        }
    }

    // ---------------- fused epilogue ----------------
    float* s_log  = reinterpret_cast<float*>(smem);           // [128][68] = 34816 B
    float* s_u    = reinterpret_cast<float*>(smem + 34816);   // [128]
    float* s_load = s_u + 128;                                // [64]
    float* s_ent  = s_load + NEXP;

    __syncthreads();   // mainloop fully done (stage 31&3=3 untouched by s_log region)
    if (tid < MT)   s_u[tid] = B2[0];
    if (tid < NEXP) s_load[tid] = 0.0f;
    if (tid == 0)   *s_ent = 0.0f;
    __syncthreads();

    // phase A: logits -> smem, hidden -> u partials
#pragma unroll
    for (int mt = 0; mt < 2; mt++) {
        float u0 = 0.0f, u1 = 0.0f;
        const int row0 = wm * 32 + mt * 16 + (lane >> 2);
#pragma unroll
        for (int nt = 0; nt < 10; nt++) {
            const int nb = wn * 80 + nt * 8 + (lane & 3) * 2;
            const bool is_logit = (wn == 0 && nt < 8);
#pragma unroll
            for (int r = 0; r < 4; r++) {
                const int n = nb + (r & 1);
                const float v = acc[mt][nt][r];
                if (is_logit) {
                    const int rl = row0 + ((r >= 2) ? 8 : 0);
                    s_log[rl * 68 + n] = v;
                } else {
                    const int h = n - 64;
                    const float hh = fmaxf(v + __ldg(B1 + h), 0.0f) * __ldg(W2 + h);
                    if (r < 2) u0 += hh; else u1 += hh;
                }
            }
        }
        u0 += __shfl_xor_sync(0xffffffffu, u0, 1);
        u0 += __shfl_xor_sync(0xffffffffu, u0, 2);
        u1 += __shfl_xor_sync(0xffffffffu, u1, 1);
        u1 += __shfl_xor_sync(0xffffffffu, u1, 2);
        if ((lane & 3) == 0) {
            atomicAdd(&s_u[row0], u0);
            atomicAdd(&s_u[row0 + 8], u1);
        }
    }
    __syncthreads();

    // phase B: logits -> global (all threads, read-only on s_log)
#pragma unroll
    for (int it = 0; it < 4; it++) {
        int t = tid + it * THREADS;
        int r = t >> 4, c4 = t & 15;
        float4 v = *reinterpret_cast<const float4*>(s_log + r * 68 + c4 * 4);
        *reinterpret_cast<float4*>(logits + (size_t)(m0 + r) * NEXP + c4 * 4) = v;
    }

    // phase D: softmax stats, 4 lanes per token x 16 experts (read-only on s_log)
    {
        const int t = tid >> 2, q = tid & 3;
        const float* row = s_log + t * 68 + q * 16;
        float xs[16];
        float mx = -INFINITY;
#pragma unroll
        for (int i = 0; i < 16; i++) { xs[i] = row[i]; mx = fmaxf(mx, xs[i]); }
        mx = fmaxf(mx, __shfl_xor_sync(0xffffffffu, mx, 1));
        mx = fmaxf(mx, __shfl_xor_sync(0xffffffffu, mx, 2));
        float se = 0.0f, sc = 0.0f;
#pragma unroll
        for (int i = 0; i < 16; i++) {
            float d = xs[i] - mx;
            float e = __expf(d);
            se += e;
            sc = fmaf(e, d, sc);
            xs[i] = e;
        }
        se += __shfl_xor_sync(0xffffffffu, se, 1);
        se += __shfl_xor_sync(0xffffffffu, se, 2);
        sc += __shfl_xor_sync(0xffffffffu, sc, 1);
        sc += __shfl_xor_sync(0xffffffffu, sc, 2);
        const float inv = 1.0f / se;
        // p values, reduced over the 8 tokens of this warp (lanes stride 4)
#pragma unroll
        for (int i = 0; i < 16; i++) {
            float p = xs[i] * inv;
            p += __shfl_xor_sync(0xffffffffu, p, 4);
            p += __shfl_xor_sync(0xffffffffu, p, 8);
            p += __shfl_xor_sync(0xffffffffu, p, 16);
            xs[i] = p;
        }
        if (lane < 4) {
#pragma unroll
            for (int i = 0; i < 16; i++) atomicAdd(&s_load[lane * 16 + i], xs[i]);
        }
        // entropy: ln(se) - sc/se per token; count each token once (q==0)
        float ent = (q == 0) ? (__logf(se) - sc * inv) : 0.0f;
        ent += __shfl_xor_sync(0xffffffffu, ent, 1);
        ent += __shfl_xor_sync(0xffffffffu, ent, 2);
        ent += __shfl_xor_sync(0xffffffffu, ent, 4);
        ent += __shfl_xor_sync(0xffffffffu, ent, 8);
        ent += __shfl_xor_sync(0xffffffffu, ent, 16);
        if (lane == 0) atomicAdd(s_ent, ent);
    }
    __syncthreads();

    // phase C: top-k + weights (tid<128), stats flush (tid in [128,193))
    if (tid < MT) {
        const int m = m0 + tid;
        const float* row = s_log + tid * 68;

        float v0 = -INFINITY, v1 = -INFINITY, v2 = -INFINITY, v3 = -INFINITY;
        int i0 = 0, i1 = 0, i2 = 0, i3 = 0;
#pragma unroll
        for (int j = 0; j < NEXP; j++) {
            float x = row[j];
            if (x > v3) {
                if (x > v0)      { v3=v2;i3=i2; v2=v1;i2=i1; v1=v0;i1=i0; v0=x;i0=j; }
                else if (x > v1) { v3=v2;i3=i2; v2=v1;i2=i1; v1=x;i1=j; }
                else if (x > v2) { v3=v2;i3=i2; v2=x;i2=j; }
                else             { v3=x;i3=j; }
            }
        }
        float u = s_u[tid];
        float cplx = 1.0f / (1.0f + expf(-u));
        int kk = (cplx > 0.5f) ? 4 : 1;
        float e0 = 1.0f;
        float e1 = (kk > 1) ? expf(v1 - v0) : 0.0f;
        float e2 = (kk > 2) ? expf(v2 - v0) : 0.0f;
        float e3 = (kk > 3) ? expf(v3 - v0) : 0.0f;
        float wi = 1.0f / (e0 + e1 + e2 + e3);

        *reinterpret_cast<float4*>(sel + (size_t)m * 4) =
            make_float4((float)i0, (float)((kk > 1) ? i1 : 0),
                        (float)((kk > 2) ? i2 : 0), (float)((kk > 3) ? i3 : 0));
        *reinterpret_cast<float4*>(wts + (size_t)m * 4) =
            make_float4(e0 * wi, e1 * wi, e2 * wi, e3 * wi);
    } else if (tid < MT + NEXP) {
        atomicAdd(&g_load[tid - MT], s_load[tid - MT]);
    } else if (tid == MT + NEXP) {
        atomicAdd(&g_ent, *s_ent);
    }
}

// ---------------- finalize ----------------
__global__ void finalize_kernel(float* __restrict__ out_var, float* __restrict__ out_ent) {
    if (threadIdx.x == 0) {
        float xs[NEXP];
        float mean = 0.0f;
        for (int e = 0; e < NEXP; e++) { xs[e] = g_load[e] * (1.0f / N_TOK); mean += xs[e]; }
        mean *= (1.0f / NEXP);
        float var = 0.0f;
        for (int e = 0; e < NEXP; e++) { float d = xs[e] - mean; var += d * d; }
        out_var[0] = var * (1.0f / (NEXP - 1));
        out_ent[0] = g_ent * (1.0f / N_TOK);
    }
}

// ---------------- launch ----------------
extern "C" void kernel_launch(void* const* d_in, const int* in_sizes, int n_in,
                              void* d_out, int out_size) {
    const float* X  = (const float*)d_in[0];
    const float* RW = (const float*)d_in[1];
    const float* W1 = (const float*)d_in[2];
    const float* B1 = (const float*)d_in[3];
    const float* W2 = (const float*)d_in[4];
    const float* B2 = (const float*)d_in[5];

    float* out    = (float*)d_out;
    float* logits = out;
    float* sel    = logits + (size_t)N_TOK * NEXP;
    float* wts    = sel + (size_t)N_TOK * 4;
    float* ovar   = wts + (size_t)N_TOK * 4;
    float* oent   = ovar + 1;

    cudaFuncSetAttribute(gemm_kernel, cudaFuncAttributeMaxDynamicSharedMemorySize, SMEM_TOTAL);

    prep_kernel<<<W_BLOCKS + X_BLOCKS, 256>>>(X, RW, W1);
    gemm_kernel<<<N_TOK / MT, THREADS, SMEM_TOTAL>>>(B1, W2, B2, logits, sel, wts);
    finalize_kernel<<<1, 32>>>(ovar, oent);
}